// round 9
// baseline (speedup 1.0000x reference)
#include <cuda_runtime.h>
#include <cstdint>

// IPLayer segment-sum via CSR: sort pair ids by atom (counting sort), then one
// warp per atom gathers and accumulates its rows in registers, writing the
// 256B output row exactly once (no global atomics on the fat payload).
// Inputs (metadata order): ind_2 (int32, N_PAIRS*2), prop (float32, N_ATOMS*128),
//                          inter (float32, N_PAIRS*64). Output: float32 N_ATOMS*64.

#define N_INTER 64
#define F4 (N_INTER / 4)          // 16 float4 per row
#define MAX_ATOMS 131072
#define MAX_PAIRS 4194304
#define SCAN_T 1024

__device__ int g_start[MAX_ATOMS + 1]; // CSR row starts (exclusive scan)
__device__ int g_cursor[MAX_ATOMS];    // counts, then running insert cursor
__device__ int g_pairid[MAX_PAIRS];    // pair ids sorted by atom

__global__ void zero_cursor_kernel(int n_atoms) {
    int i = blockIdx.x * blockDim.x + threadIdx.x;
    if (i < n_atoms) g_cursor[i] = 0;
}

__global__ void hist_kernel(const int2* __restrict__ ind2, int n_pairs) {
    int i = blockIdx.x * blockDim.x + threadIdx.x;
    if (i < n_pairs) {
        int a = __ldg(&ind2[i]).x;
        atomicAdd(&g_cursor[a], 1);
    }
}

// Single-block two-pass scan: per-thread chunk sums, Hillis-Steele over 1024
// partials in smem, then rewrite g_cursor (and g_start) with exclusive offsets.
__global__ void __launch_bounds__(SCAN_T) scan_kernel(int n_atoms) {
    __shared__ int sm[SCAN_T];
    int t = threadIdx.x;
    int chunk = (n_atoms + SCAN_T - 1) / SCAN_T;
    int lo = t * chunk;
    int hi = lo + chunk < n_atoms ? lo + chunk : n_atoms;

    int sum = 0;
    for (int i = lo; i < hi; i++) sum += g_cursor[i];
    sm[t] = sum;
    __syncthreads();

    for (int off = 1; off < SCAN_T; off <<= 1) {
        int v = (t >= off) ? sm[t - off] : 0;
        __syncthreads();
        sm[t] += v;
        __syncthreads();
    }

    int run = (t == 0) ? 0 : sm[t - 1];
    for (int i = lo; i < hi; i++) {
        int c = g_cursor[i];
        g_start[i] = run;
        g_cursor[i] = run;   // becomes the insert cursor for permute
        run += c;
    }
    if (t == SCAN_T - 1) g_start[n_atoms] = sm[SCAN_T - 1];
}

__global__ void permute_kernel(const int2* __restrict__ ind2, int n_pairs) {
    int i = blockIdx.x * blockDim.x + threadIdx.x;
    if (i < n_pairs) {
        int a = __ldg(&ind2[i]).x;
        int pos = atomicAdd(&g_cursor[a], 1);
        g_pairid[pos] = i;
    }
}

__device__ __forceinline__ void f4add(float4& a, const float4& b) {
    a.x += b.x; a.y += b.y; a.z += b.z; a.w += b.w;
}

// One warp per atom. lane = h*16 + c: c = float4 chunk of the 64-float row,
// h = which half of the pair list (even/odd slots). Unrolled 4x per half
// (8 pairs per warp-iteration) for MLP; two accumulators break FADD chains.
// Final cross-half combine via shfl_xor(16); lanes 0..15 store the row once.
__global__ void __launch_bounds__(256) gather_kernel(
        const float4* __restrict__ inter,
        float* __restrict__ out,
        int n_atoms) {
    int gw = (blockIdx.x * blockDim.x + threadIdx.x) >> 5;
    if (gw >= n_atoms) return;
    int lane = threadIdx.x & 31;
    int c = lane & 15;
    int h = lane >> 4;

    int s = g_start[gw];
    int e = g_start[gw + 1];

    float4 a0 = make_float4(0.f, 0.f, 0.f, 0.f);
    float4 a1 = make_float4(0.f, 0.f, 0.f, 0.f);

    int k = s + h;
    for (; k + 6 < e; k += 8) {
        int p0 = __ldg(&g_pairid[k]);
        int p1 = __ldg(&g_pairid[k + 2]);
        int p2 = __ldg(&g_pairid[k + 4]);
        int p3 = __ldg(&g_pairid[k + 6]);
        float4 v0 = inter[(size_t)p0 * F4 + c];
        float4 v1 = inter[(size_t)p1 * F4 + c];
        float4 v2 = inter[(size_t)p2 * F4 + c];
        float4 v3 = inter[(size_t)p3 * F4 + c];
        f4add(a0, v0);
        f4add(a1, v1);
        f4add(a0, v2);
        f4add(a1, v3);
    }
    for (; k < e; k += 2) {
        int p = __ldg(&g_pairid[k]);
        float4 v = inter[(size_t)p * F4 + c];
        f4add(a0, v);
    }

    f4add(a0, a1);
    a0.x += __shfl_xor_sync(0xFFFFFFFFu, a0.x, 16);
    a0.y += __shfl_xor_sync(0xFFFFFFFFu, a0.y, 16);
    a0.z += __shfl_xor_sync(0xFFFFFFFFu, a0.z, 16);
    a0.w += __shfl_xor_sync(0xFFFFFFFFu, a0.w, 16);

    if (h == 0)
        *reinterpret_cast<float4*>(out + (size_t)gw * N_INTER + c * 4) = a0;
}

extern "C" void kernel_launch(void* const* d_in, const int* in_sizes, int n_in,
                              void* d_out, int out_size) {
    const int2*   ind2  = (const int2*)d_in[0];
    const float4* inter = (const float4*)d_in[2];
    float*        out   = (float*)d_out;

    int n_pairs = in_sizes[0] / 2;
    int n_atoms = out_size / N_INTER;
    if (n_atoms > MAX_ATOMS) n_atoms = MAX_ATOMS;     // fixed-shape guard
    if (n_pairs > MAX_PAIRS) n_pairs = MAX_PAIRS;

    zero_cursor_kernel<<<(n_atoms + 255) / 256, 256>>>(n_atoms);
    hist_kernel<<<(n_pairs + 255) / 256, 256>>>(ind2, n_pairs);
    scan_kernel<<<1, SCAN_T>>>(n_atoms);
    permute_kernel<<<(n_pairs + 255) / 256, 256>>>(ind2, n_pairs);

    long long gthreads = (long long)n_atoms * 32;
    int gblocks = (int)((gthreads + 255) / 256);
    gather_kernel<<<gblocks, 256>>>(inter, out, n_atoms);
}

// round 10
// speedup vs baseline: 1.9847x; 1.9847x over previous
#include <cuda_runtime.h>
#include <cstdint>

// IPLayer segment-sum: out[atom][g] += inter[pair][g] for atom = ind_2[pair][0]
// Inputs (metadata order): ind_2 (int32, N_PAIRS*2), prop (float32, N_ATOMS*128),
//                          inter (float32, N_PAIRS*64). Output: float32 N_ATOMS*64.
//
// Champion scatter design (R7) + non-temporal (__ldcs) loads on the streaming
// operands so the 870MB one-touch stream doesn't evict the L2-resident output
// that the red.global.add RMWs depend on.

#define N_INTER 64
#define PP      4   // pairs per thread

__global__ void zero_out_kernel(float4* __restrict__ out, int n4) {
    int i = blockIdx.x * blockDim.x + threadIdx.x;
    if (i < n4) out[i] = make_float4(0.f, 0.f, 0.f, 0.f);
}

// 16 lanes cover one pair's 256B row (one float4 chunk per lane, dense sectors).
// Each thread handles PP consecutive pairs for the SAME chunk c: independent
// index + row loads issued up front (MLP>=4), then PP red.global.add.v4.f32.
__global__ void seg_red_kernel(const int* __restrict__ ind2,
                               const float4* __restrict__ inter,
                               float* __restrict__ out,
                               int n_pairs) {
    int i = blockIdx.x * blockDim.x + threadIdx.x;
    int g = i >> 4;          // pair-group index (PP pairs)
    int c = i & 15;          // float4 chunk within the 64-float row
    int p0 = g * PP;
    if (p0 >= n_pairs) return;

    if (p0 + PP <= n_pairs) {
        // Streaming (evict-first) index loads.
        int a0 = __ldcs(&ind2[2 * (p0 + 0)]);
        int a1 = __ldcs(&ind2[2 * (p0 + 1)]);
        int a2 = __ldcs(&ind2[2 * (p0 + 2)]);
        int a3 = __ldcs(&ind2[2 * (p0 + 3)]);

        // Streaming (evict-first) row loads: one-touch data, keep out of L2.
        const float4* src = inter + (size_t)p0 * (N_INTER / 4) + c;
        float4 v0 = __ldcs(src + 0 * (N_INTER / 4));
        float4 v1 = __ldcs(src + 1 * (N_INTER / 4));
        float4 v2 = __ldcs(src + 2 * (N_INTER / 4));
        float4 v3 = __ldcs(src + 3 * (N_INTER / 4));

        float* d0 = out + (size_t)a0 * N_INTER + c * 4;
        float* d1 = out + (size_t)a1 * N_INTER + c * 4;
        float* d2 = out + (size_t)a2 * N_INTER + c * 4;
        float* d3 = out + (size_t)a3 * N_INTER + c * 4;

        asm volatile("red.global.add.v4.f32 [%0], {%1,%2,%3,%4};"
                     :: "l"(d0), "f"(v0.x), "f"(v0.y), "f"(v0.z), "f"(v0.w) : "memory");
        asm volatile("red.global.add.v4.f32 [%0], {%1,%2,%3,%4};"
                     :: "l"(d1), "f"(v1.x), "f"(v1.y), "f"(v1.z), "f"(v1.w) : "memory");
        asm volatile("red.global.add.v4.f32 [%0], {%1,%2,%3,%4};"
                     :: "l"(d2), "f"(v2.x), "f"(v2.y), "f"(v2.z), "f"(v2.w) : "memory");
        asm volatile("red.global.add.v4.f32 [%0], {%1,%2,%3,%4};"
                     :: "l"(d3), "f"(v3.x), "f"(v3.y), "f"(v3.z), "f"(v3.w) : "memory");
    } else {
        // Tail: per-pair.
        for (int p = p0; p < n_pairs; p++) {
            int a = __ldcs(&ind2[2 * p]);
            float4 v = __ldcs(&inter[(size_t)p * (N_INTER / 4) + c]);
            float* dst = out + (size_t)a * N_INTER + c * 4;
            asm volatile("red.global.add.v4.f32 [%0], {%1,%2,%3,%4};"
                         :: "l"(dst), "f"(v.x), "f"(v.y), "f"(v.z), "f"(v.w) : "memory");
        }
    }
}

extern "C" void kernel_launch(void* const* d_in, const int* in_sizes, int n_in,
                              void* d_out, int out_size) {
    const int*    ind2  = (const int*)d_in[0];
    const float4* inter = (const float4*)d_in[2];
    float*        out   = (float*)d_out;

    int n_pairs = in_sizes[0] / 2;

    // Zero the (poisoned) output buffer; plain stores so the lines allocate
    // in L2 and stay there for the atomic phase.
    int n4 = out_size / 4;
    zero_out_kernel<<<(n4 + 255) / 256, 256>>>((float4*)out, n4);

    // Scatter-add: 16 lanes x PP pairs per thread.
    int n_groups = (n_pairs + PP - 1) / PP;
    long long n_work = (long long)n_groups * 16;
    int blocks = (int)((n_work + 255) / 256);
    seg_red_kernel<<<blocks, 256>>>(ind2, inter, out, n_pairs);
}